// round 7
// baseline (speedup 1.0000x reference)
#include <cuda_runtime.h>

#define NB 64
#define NL 512
#define TILES 8
#define KT (NL / 2 / TILES)    // 32 offsets per block
#define NTHREADS 256
#define NBLOCKS (NB * TILES)   // 512

__device__ float g_sqrtsum[NBLOCKS];   // per-chunk sum of sqrt(s1*s2), triangle-weighted
__device__ float g_closed[NB];         // per-batch closed-form full-matrix sum of (s1+s2)
__device__ unsigned int g_sync = 0;

__device__ __forceinline__ float sqrt_approx(float x) {
    float r; asm("sqrt.approx.f32 %0, %1;" : "=f"(r) : "f"(x)); return r;
}

// Pair enumeration: (j, (j+k) mod L), k = 1..L/2.  k in [1, L/2) covers every
// unordered pair exactly once; k = L/2 covers each {j, j+L/2} pair twice ->
// weight 1/2.  Perfectly uniform per-thread work, no triangle imbalance,
// and HALF the pairs of the full-matrix formulation.
//
// Per pair (Gram form, s = squared distance):  err = s1 + s2 - 2*sqrt(s1*s2)
// Closed form (exact, O(L)): sum_{i,j} (s1+s2) = 2L*Sum(n) - 2|Sum(x)|^2 per field.
// 2 * sumsq_triangle = closed - 4 * sum_tri sqrt(s1*s2).
__global__ void __launch_bounds__(NTHREADS) fused_kernel(
    const float* __restrict__ inp, const float* __restrict__ tgt,
    float* __restrict__ out)
{
    __shared__ float4 sIn[NL];         // {x, y, z, |x|^2} input CA
    __shared__ float4 sTg[NL];         // {x, y, z, |x|^2} target CA
    __shared__ float swarp[NTHREADS / 32];
    __shared__ float sred[8][8];
    __shared__ int s_last;

    const int b   = blockIdx.x / TILES;
    const int t   = blockIdx.x % TILES;
    const int tid = threadIdx.x;

    // ---- stage CA coords + norms (atom 1 -> floats 3..5 of 9/residue)
    for (int k = tid; k < NL; k += NTHREADS) {
        int base = (b * NL + k) * 9 + 3;
        float ax = inp[base + 0], ay = inp[base + 1], az = inp[base + 2];
        float cx = tgt[base + 0], cy = tgt[base + 1], cz = tgt[base + 2];
        sIn[k] = make_float4(ax, ay, az, fmaf(ax, ax, fmaf(ay, ay, az * az)));
        sTg[k] = make_float4(cx, cy, cz, fmaf(cx, cx, fmaf(cy, cy, cz * cz)));
    }
    __syncthreads();

    // ---- batch stats (tile-0 block only): Sum(x), Sum(n) -> closed form
    if (t == 0) {
        float4 pI, pT;
        {
            float4 a = sIn[tid], b2 = sIn[tid + NTHREADS];
            pI = make_float4(a.x + b2.x, a.y + b2.y, a.z + b2.z, a.w + b2.w);
            float4 c = sTg[tid], d = sTg[tid + NTHREADS];
            pT = make_float4(c.x + d.x, c.y + d.y, c.z + d.z, c.w + d.w);
        }
        for (int off = 16; off > 0; off >>= 1) {
            pI.x += __shfl_down_sync(0xFFFFFFFFu, pI.x, off);
            pI.y += __shfl_down_sync(0xFFFFFFFFu, pI.y, off);
            pI.z += __shfl_down_sync(0xFFFFFFFFu, pI.z, off);
            pI.w += __shfl_down_sync(0xFFFFFFFFu, pI.w, off);
            pT.x += __shfl_down_sync(0xFFFFFFFFu, pT.x, off);
            pT.y += __shfl_down_sync(0xFFFFFFFFu, pT.y, off);
            pT.z += __shfl_down_sync(0xFFFFFFFFu, pT.z, off);
            pT.w += __shfl_down_sync(0xFFFFFFFFu, pT.w, off);
        }
        if ((tid & 31) == 0) {
            int w = tid >> 5;
            sred[w][0] = pI.x; sred[w][1] = pI.y; sred[w][2] = pI.z; sred[w][3] = pI.w;
            sred[w][4] = pT.x; sred[w][5] = pT.y; sred[w][6] = pT.z; sred[w][7] = pT.w;
        }
        __syncthreads();
        if (tid == 0) {
            float v[8];
#pragma unroll
            for (int q = 0; q < 8; ++q) {
                float s = sred[0][q];
#pragma unroll
                for (int w = 1; w < 8; ++w) s += sred[w][q];
                v[q] = s;
            }
            float c1 = 2.0f * NL * v[3] - 2.0f * (v[0]*v[0] + v[1]*v[1] + v[2]*v[2]);
            float c2 = 2.0f * NL * v[7] - 2.0f * (v[4]*v[4] + v[5]*v[5] + v[6]*v[6]);
            g_closed[b] = c1 + c2;
        }
    }

    // ---- each thread owns 2 fixed j's: constants prescaled by -2
    const int j0 = tid, j1 = tid + NTHREADS;
    const float4 J0i = sIn[j0], J0t = sTg[j0];
    const float4 J1i = sIn[j1], J1t = sTg[j1];
    const float a0x = -2.f*J0i.x, a0y = -2.f*J0i.y, a0z = -2.f*J0i.z, n0 = J0i.w;
    const float c0x = -2.f*J0t.x, c0y = -2.f*J0t.y, c0z = -2.f*J0t.z, m0 = J0t.w;
    const float a1x = -2.f*J1i.x, a1y = -2.f*J1i.y, a1z = -2.f*J1i.z, n1 = J1i.w;
    const float c1x = -2.f*J1t.x, c1y = -2.f*J1t.y, c1z = -2.f*J1t.z, m1 = J1t.w;

    float acc = 0.0f;

    const int k0   = 1 + KT * t;
    const int klim = (t == TILES - 1) ? (NL / 2) : (k0 + KT);  // exclusive; k=256 handled below
#pragma unroll 4
    for (int k = k0; k < klim; ++k) {
        {
            const int i = (j0 + k) & (NL - 1);
            const float4 I = sIn[i];
            const float4 T = sTg[i];
            float s1 = fmaf(I.x, a0x, fmaf(I.y, a0y, fmaf(I.z, a0z, I.w))) + n0;
            float s2 = fmaf(T.x, c0x, fmaf(T.y, c0y, fmaf(T.z, c0z, T.w))) + m0;
            acc += sqrt_approx(fmaxf(s1 * s2, 0.0f));
        }
        {
            const int i = (j1 + k) & (NL - 1);
            const float4 I = sIn[i];
            const float4 T = sTg[i];
            float s1 = fmaf(I.x, a1x, fmaf(I.y, a1y, fmaf(I.z, a1z, I.w))) + n1;
            float s2 = fmaf(T.x, c1x, fmaf(T.y, c1y, fmaf(T.z, c1z, T.w))) + m1;
            acc += sqrt_approx(fmaxf(s1 * s2, 0.0f));
        }
    }

    // k = L/2: each unordered pair {j, j+L/2} appears twice across j -> weight 1/2
    if (t == TILES - 1) {
        float accH = 0.0f;
        {
            const int i = (j0 + NL / 2) & (NL - 1);
            const float4 I = sIn[i];
            const float4 T = sTg[i];
            float s1 = fmaf(I.x, a0x, fmaf(I.y, a0y, fmaf(I.z, a0z, I.w))) + n0;
            float s2 = fmaf(T.x, c0x, fmaf(T.y, c0y, fmaf(T.z, c0z, T.w))) + m0;
            accH += sqrt_approx(fmaxf(s1 * s2, 0.0f));
        }
        {
            const int i = (j1 + NL / 2) & (NL - 1);
            const float4 I = sIn[i];
            const float4 T = sTg[i];
            float s1 = fmaf(I.x, a1x, fmaf(I.y, a1y, fmaf(I.z, a1z, I.w))) + n1;
            float s2 = fmaf(T.x, c1x, fmaf(T.y, c1y, fmaf(T.z, c1z, T.w))) + m1;
            accH += sqrt_approx(fmaxf(s1 * s2, 0.0f));
        }
        acc = fmaf(0.5f, accH, acc);
    }

    // ---- block reduce the (triangle) sqrt-sum
    for (int off = 16; off > 0; off >>= 1)
        acc += __shfl_down_sync(0xFFFFFFFFu, acc, off);
    if ((tid & 31) == 0) swarp[tid >> 5] = acc;
    __syncthreads();
    if (tid < (NTHREADS / 32)) {
        float v = swarp[tid];
        for (int off = (NTHREADS / 64); off > 0; off >>= 1)
            v += __shfl_down_sync(0xFFu, v, off);
        if (tid == 0) g_sqrtsum[blockIdx.x] = v;
    }

    // ---- last block computes the final scalar (no second launch)
    if (tid == 0) {
        __threadfence();
        unsigned int old = atomicAdd(&g_sync, 1u);
        s_last = (old == (unsigned)(gridDim.x - 1));
    }
    __syncthreads();

    if (s_last) {
        float res = 0.0f;
        if (tid < NB) {
            float sq = 0.0f;
#pragma unroll
            for (int k = 0; k < TILES; ++k)
                sq += g_sqrtsum[tid * TILES + k];
            // 2 * sumsq_triangle = closed_full_matrix - 4 * sqrtsum_triangle
            float total = g_closed[tid] - 4.0f * sq;
            res = sqrtf(total + 1e-6f);
            res *= (1.0f / (sqrtf((float)NL * (float)(NL - 1)) * (float)NL));
        }
        for (int off = 16; off > 0; off >>= 1)
            res += __shfl_down_sync(0xFFFFFFFFu, res, off);
        if ((tid & 31) == 0) swarp[tid >> 5] = res;
        __syncthreads();
        if (tid == 0) {
            out[0] = (swarp[0] + swarp[1]) * (1.0f / (float)NB);
            g_sync = 0;   // reset for next graph replay
        }
    }
}

extern "C" void kernel_launch(void* const* d_in, const int* in_sizes, int n_in,
                              void* d_out, int out_size)
{
    const float* inp = (const float*)d_in[0];
    const float* tgt = (const float*)d_in[1];
    float* out = (float*)d_out;
    fused_kernel<<<NBLOCKS, NTHREADS>>>(inp, tgt, out);
}